// round 2
// baseline (speedup 1.0000x reference)
#include <cuda_runtime.h>

#define NPATHS 100000
#define NLINKS 10000

// ---------------- persistent device state (no allocations allowed) ----------
__device__ __align__(16) float g_link_state[NLINKS * 32];
__device__ __align__(16) float g_path_state[NPATHS * 32];
__device__ __align__(16) float g_m[NLINKS * 32];          // segment sums
__device__ __align__(16) float g_LG[NLINKS * 96];         // link_state @ Wp + biases

// ---------------- fast activations ----------------
__device__ __forceinline__ float sigmoidf_(float x) {
    return __fdividef(1.0f, 1.0f + __expf(-x));
}
__device__ __forceinline__ float tanhfast_(float x) {
    float e = __expf(2.0f * x);
    return 1.0f - __fdividef(2.0f, e + 1.0f);
}
__device__ __forceinline__ float seluf_(float x) {
    const float sc = 1.0507009873554805f;
    const float al = 1.6732632423543772f;
    return x > 0.0f ? sc * x : sc * al * (__expf(x) - 1.0f);
}

__device__ __forceinline__ void red_add_f4(float* p, float a, float b, float c, float d) {
#if defined(__CUDA_ARCH__) && (__CUDA_ARCH__ >= 900)
    atomicAdd(reinterpret_cast<float4*>(p), make_float4(a, b, c, d));
#else
    atomicAdd(p + 0, a); atomicAdd(p + 1, b); atomicAdd(p + 2, c); atomicAdd(p + 3, d);
#endif
}

// ---------------- init: states, m=0, initial LG ----------------
__global__ void k_init(const float* __restrict__ cap, const float* __restrict__ traffic,
                       const float* __restrict__ Wp, const float* __restrict__ bp) {
    int idx = blockIdx.x * blockDim.x + threadIdx.x;
    if (idx < NPATHS * 32)
        g_path_state[idx] = ((idx & 31) == 0) ? traffic[idx >> 5] : 0.0f;
    if (idx < NLINKS * 32) {
        g_link_state[idx] = ((idx & 31) == 0) ? cap[idx >> 5] : 0.0f;
        g_m[idx] = 0.0f;
    }
    if (idx < NLINKS * 96) {
        int l = idx / 96;
        int j = idx - l * 96;
        // initial link_state has only col 0 nonzero (= capacity)
        float v = cap[l] * Wp[j] + bp[j];        // input bias bp[0]
        if (j < 64) v += bp[96 + j];             // fold recurrent bias bp[1] for z,r gates
        g_LG[idx] = v;
    }
}

// ---------------- path phase: 8 GRU steps + fused atomic segment-sum --------
__global__ void __launch_bounds__(128)
k_path(const int* __restrict__ links, const float* __restrict__ Up,
       const float* __restrict__ bp) {
    __shared__ float sUp[32 * 96];    // recurrent weights
    __shared__ float sb1h[32];        // bp[1] h-gate slice
    __shared__ float sh[32 * 132];    // h, layout [k][tid] with padded transpose-load stride

    const int tid = threadIdx.x;
    for (int i = tid; i < 3072; i += 128) sUp[i] = Up[i];
    if (tid < 32) sb1h[tid] = bp[96 + 64 + tid];

    const int p0 = blockIdx.x * 128;
    // coalesced transpose stage of path_state tile into smem [c][r]
    for (int i = tid; i < 4096; i += 128) {
        int r = i >> 5, c = i & 31;
        int pp = p0 + r;
        sh[c * 132 + r] = (pp < NPATHS) ? g_path_state[pp * 32 + c] : 0.0f;
    }
    __syncthreads();

    const int p = p0 + tid;
    const bool valid = (p < NPATHS);

    int lk[8];
    if (valid) {
        const int4* lp = reinterpret_cast<const int4*>(links + p * 8);
        int4 a = __ldg(lp), b = __ldg(lp + 1);
        lk[0] = a.x; lk[1] = a.y; lk[2] = a.z; lk[3] = a.w;
        lk[4] = b.x; lk[5] = b.y; lk[6] = b.z; lk[7] = b.w;
    }

    if (valid) {
        #pragma unroll 1
        for (int s = 0; s < 8; s++) {
            const float4* lg = reinterpret_cast<const float4*>(g_LG + lk[s] * 96);

            float az[32], ar[32], ah[32];
            #pragma unroll
            for (int c = 0; c < 8; c++) {
                float4 v = __ldg(lg + c);
                az[4*c+0] = v.x; az[4*c+1] = v.y; az[4*c+2] = v.z; az[4*c+3] = v.w;
            }
            #pragma unroll
            for (int c = 0; c < 8; c++) {
                float4 v = __ldg(lg + 8 + c);
                ar[4*c+0] = v.x; ar[4*c+1] = v.y; ar[4*c+2] = v.z; ar[4*c+3] = v.w;
            }
            #pragma unroll
            for (int j = 0; j < 32; j++) ah[j] = sb1h[j];

            // fused recurrent matvec: all three gates in one k-pass
            #pragma unroll 1
            for (int k = 0; k < 32; k++) {
                float hk = sh[k * 132 + tid];
                const float4* w = reinterpret_cast<const float4*>(sUp + k * 96);
                #pragma unroll
                for (int c = 0; c < 8; c++) {
                    float4 wv = w[c];
                    az[4*c+0] = fmaf(hk, wv.x, az[4*c+0]);
                    az[4*c+1] = fmaf(hk, wv.y, az[4*c+1]);
                    az[4*c+2] = fmaf(hk, wv.z, az[4*c+2]);
                    az[4*c+3] = fmaf(hk, wv.w, az[4*c+3]);
                }
                #pragma unroll
                for (int c = 0; c < 8; c++) {
                    float4 wv = w[8 + c];
                    ar[4*c+0] = fmaf(hk, wv.x, ar[4*c+0]);
                    ar[4*c+1] = fmaf(hk, wv.y, ar[4*c+1]);
                    ar[4*c+2] = fmaf(hk, wv.z, ar[4*c+2]);
                    ar[4*c+3] = fmaf(hk, wv.w, ar[4*c+3]);
                }
                #pragma unroll
                for (int c = 0; c < 8; c++) {
                    float4 wv = w[16 + c];
                    ah[4*c+0] = fmaf(hk, wv.x, ah[4*c+0]);
                    ah[4*c+1] = fmaf(hk, wv.y, ah[4*c+1]);
                    ah[4*c+2] = fmaf(hk, wv.z, ah[4*c+2]);
                    ah[4*c+3] = fmaf(hk, wv.w, ah[4*c+3]);
                }
            }

            // gates + state update + fused segment-sum scatter
            float* mrow = g_m + lk[s] * 32;
            #pragma unroll
            for (int c = 0; c < 8; c++) {
                float4 g = __ldg(lg + 16 + c);
                float nh[4];
                #pragma unroll
                for (int u = 0; u < 4; u++) {
                    int j = 4 * c + u;
                    float z  = sigmoidf_(az[j]);
                    float r  = sigmoidf_(ar[j]);
                    float gv = (&g.x)[u];                  // LG h-part (x@Wp_h + bp0_h)
                    float cc = tanhfast_(gv + r * ah[j]);
                    float ho = sh[j * 132 + tid];
                    float hn = cc + z * (ho - cc);         // z*h + (1-z)*c
                    sh[j * 132 + tid] = hn;
                    nh[u] = hn;
                }
                red_add_f4(mrow + 4 * c, nh[0], nh[1], nh[2], nh[3]);
            }
        }
    }

    __syncthreads();
    for (int i = tid; i < 4096; i += 128) {
        int r = i >> 5, c = i & 31;
        int pp = p0 + r;
        if (pp < NPATHS) g_path_state[pp * 32 + c] = sh[c * 132 + r];
    }
}

// ---------------- link phase: link GRU + recompute LG + zero m --------------
__global__ void __launch_bounds__(128)
k_link(const float* __restrict__ Wl, const float* __restrict__ Ul,
       const float* __restrict__ bl, const float* __restrict__ Wp,
       const float* __restrict__ bp) {
    __shared__ float sWl[3072], sUl[3072], sWp[3072];
    __shared__ float sbl[192], sbp[192];
    const int tid = threadIdx.x;
    for (int i = tid; i < 3072; i += 128) { sWl[i] = Wl[i]; sUl[i] = Ul[i]; sWp[i] = Wp[i]; }
    for (int i = tid; i < 192; i += 128)  { sbl[i] = bl[i]; sbp[i] = bp[i]; }
    __syncthreads();

    const int l = blockIdx.x * 128 + tid;
    if (l >= NLINKS) return;

    const float* mrow = g_m + l * 32;
    float* hrow = g_link_state + l * 32;

    float az[32], ar[32], axh[32], ahh[32];
    #pragma unroll
    for (int j = 0; j < 32; j++) {
        az[j]  = sbl[j]       + sbl[96 + j];
        ar[j]  = sbl[32 + j]  + sbl[128 + j];
        axh[j] = sbl[64 + j];
        ahh[j] = sbl[160 + j];
    }

    #pragma unroll 1
    for (int k = 0; k < 32; k++) {
        float mk = __ldg(mrow + k);
        float hk = __ldg(hrow + k);
        const float4* wl = reinterpret_cast<const float4*>(sWl + k * 96);
        const float4* ul = reinterpret_cast<const float4*>(sUl + k * 96);
        #pragma unroll
        for (int c = 0; c < 8; c++) {
            float4 w = wl[c], u = ul[c];
            az[4*c+0] = fmaf(mk, w.x, fmaf(hk, u.x, az[4*c+0]));
            az[4*c+1] = fmaf(mk, w.y, fmaf(hk, u.y, az[4*c+1]));
            az[4*c+2] = fmaf(mk, w.z, fmaf(hk, u.z, az[4*c+2]));
            az[4*c+3] = fmaf(mk, w.w, fmaf(hk, u.w, az[4*c+3]));
        }
        #pragma unroll
        for (int c = 0; c < 8; c++) {
            float4 w = wl[8 + c], u = ul[8 + c];
            ar[4*c+0] = fmaf(mk, w.x, fmaf(hk, u.x, ar[4*c+0]));
            ar[4*c+1] = fmaf(mk, w.y, fmaf(hk, u.y, ar[4*c+1]));
            ar[4*c+2] = fmaf(mk, w.z, fmaf(hk, u.z, ar[4*c+2]));
            ar[4*c+3] = fmaf(mk, w.w, fmaf(hk, u.w, ar[4*c+3]));
        }
        #pragma unroll
        for (int c = 0; c < 8; c++) {
            float4 w = wl[16 + c], u = ul[16 + c];
            axh[4*c+0] = fmaf(mk, w.x, axh[4*c+0]);
            axh[4*c+1] = fmaf(mk, w.y, axh[4*c+1]);
            axh[4*c+2] = fmaf(mk, w.z, axh[4*c+2]);
            axh[4*c+3] = fmaf(mk, w.w, axh[4*c+3]);
            ahh[4*c+0] = fmaf(hk, u.x, ahh[4*c+0]);
            ahh[4*c+1] = fmaf(hk, u.y, ahh[4*c+1]);
            ahh[4*c+2] = fmaf(hk, u.z, ahh[4*c+2]);
            ahh[4*c+3] = fmaf(hk, u.w, ahh[4*c+3]);
        }
    }

    float hn[32];
    #pragma unroll
    for (int j = 0; j < 32; j++) {
        float z  = sigmoidf_(az[j]);
        float r  = sigmoidf_(ar[j]);
        float cc = tanhfast_(axh[j] + r * ahh[j]);
        float ho = __ldg(hrow + j);
        hn[j] = cc + z * (ho - cc);
    }

    float4* h4 = reinterpret_cast<float4*>(hrow);
    float4* m4 = reinterpret_cast<float4*>(g_m + l * 32);
    #pragma unroll
    for (int c = 0; c < 8; c++) {
        h4[c] = make_float4(hn[4*c], hn[4*c+1], hn[4*c+2], hn[4*c+3]);
        m4[c] = make_float4(0.f, 0.f, 0.f, 0.f);   // reset for next iteration
    }

    // recompute LG = new_link_state @ Wp + biases for next path phase
    float4* lg4 = reinterpret_cast<float4*>(g_LG + l * 96);
    #pragma unroll 1
    for (int jc = 0; jc < 24; jc++) {
        int j = 4 * jc;
        float a0 = sbp[j + 0], a1 = sbp[j + 1], a2 = sbp[j + 2], a3 = sbp[j + 3];
        if (jc < 16) { a0 += sbp[96+j+0]; a1 += sbp[96+j+1]; a2 += sbp[96+j+2]; a3 += sbp[96+j+3]; }
        #pragma unroll
        for (int k = 0; k < 32; k++) {
            float4 w = reinterpret_cast<const float4*>(sWp + k * 96)[jc];
            a0 = fmaf(hn[k], w.x, a0);
            a1 = fmaf(hn[k], w.y, a1);
            a2 = fmaf(hn[k], w.z, a2);
            a3 = fmaf(hn[k], w.w, a3);
        }
        lg4[jc] = make_float4(a0, a1, a2, a3);
    }
}

// ---------------- readout: selu MLP + final dense, warp handles 8 paths ----
__global__ void __launch_bounds__(128)
k_readout(const float* __restrict__ D1, const float* __restrict__ b1,
          const float* __restrict__ D2, const float* __restrict__ b2,
          const float* __restrict__ Wf, const float* __restrict__ bf,
          float* __restrict__ out) {
    __shared__ float sx1[4 * 8 * 256];   // per-warp [path][k] hidden1
    const int tid = threadIdx.x;
    const int lane = tid & 31, warp = tid >> 5;
    const int pbase = blockIdx.x * 32 + warp * 8;   // 100000 % 32 == 0, no guards
    float* myx1 = sx1 + warp * 2048;

    // ---- layer 1: 32 -> 256 + selu ----
    #pragma unroll 1
    for (int p = 0; p < 8; p++) {
        float hown = g_path_state[(pbase + p) * 32 + lane];
        float acc[8];
        #pragma unroll
        for (int i = 0; i < 8; i++) acc[i] = __ldg(b1 + lane + 32 * i);
        #pragma unroll 1
        for (int k = 0; k < 32; k++) {
            float hk = __shfl_sync(0xffffffffu, hown, k);
            const float* d1 = D1 + k * 256 + lane;
            #pragma unroll
            for (int i = 0; i < 8; i++) acc[i] = fmaf(hk, __ldg(d1 + 32 * i), acc[i]);
        }
        #pragma unroll
        for (int i = 0; i < 8; i++) myx1[p * 256 + lane + 32 * i] = seluf_(acc[i]);
    }
    __syncwarp();

    // ---- layer 2: 256 -> 256, register-reuse of D2 row across 8 paths ----
    float a2[64];
    #pragma unroll
    for (int i = 0; i < 8; i++) {
        float bv = __ldg(b2 + lane + 32 * i);
        #pragma unroll
        for (int p = 0; p < 8; p++) a2[p * 8 + i] = bv;
    }
    #pragma unroll 1
    for (int k = 0; k < 256; k++) {
        float w[8];
        const float* d2 = D2 + k * 256 + lane;
        #pragma unroll
        for (int i = 0; i < 8; i++) w[i] = __ldg(d2 + 32 * i);
        #pragma unroll
        for (int p = 0; p < 8; p++) {
            float xk = myx1[p * 256 + k];
            #pragma unroll
            for (int i = 0; i < 8; i++) a2[p * 8 + i] = fmaf(xk, w[i], a2[p * 8 + i]);
        }
    }

    // ---- selu + final dense on concat(x2, h) ----
    const float2* Wf2 = reinterpret_cast<const float2*>(Wf);
    float2 wfh = __ldg(Wf2 + 256 + lane);
    float bf0 = __ldg(bf), bf1 = __ldg(bf + 1);
    #pragma unroll 1
    for (int p = 0; p < 8; p++) {
        int pp = pbase + p;
        float hv = __ldg(&g_path_state[pp * 32 + lane]);
        float s0 = hv * wfh.x, s1 = hv * wfh.y;
        #pragma unroll
        for (int i = 0; i < 8; i++) {
            float x2 = seluf_(a2[p * 8 + i]);
            float2 wf = __ldg(Wf2 + lane + 32 * i);
            s0 = fmaf(x2, wf.x, s0);
            s1 = fmaf(x2, wf.y, s1);
        }
        #pragma unroll
        for (int off = 16; off; off >>= 1) {
            s0 += __shfl_xor_sync(0xffffffffu, s0, off);
            s1 += __shfl_xor_sync(0xffffffffu, s1, off);
        }
        if (lane == 0)
            reinterpret_cast<float2*>(out)[pp] = make_float2(s0 + bf0, s1 + bf1);
    }
}

// ---------------- launch ----------------
extern "C" void kernel_launch(void* const* d_in, const int* in_sizes, int n_in,
                              void* d_out, int out_size) {
    const float* cap     = (const float*)d_in[0];
    const float* traffic = (const float*)d_in[1];
    const int*   links   = (const int*)  d_in[2];
    // d_in[3]=paths, d_in[4]=seqs — structure is known (p = e/8, s = e%8), unused
    const float* Wp = (const float*)d_in[5];
    const float* Up = (const float*)d_in[6];
    const float* bp = (const float*)d_in[7];
    const float* Wl = (const float*)d_in[8];
    const float* Ul = (const float*)d_in[9];
    const float* bl = (const float*)d_in[10];
    const float* D1 = (const float*)d_in[11];
    const float* b1 = (const float*)d_in[12];
    const float* D2 = (const float*)d_in[13];
    const float* b2 = (const float*)d_in[14];
    const float* Wf = (const float*)d_in[15];
    const float* bf = (const float*)d_in[16];
    float* out = (float*)d_out;

    k_init<<<(NPATHS * 32 + 255) / 256, 256>>>(cap, traffic, Wp, bp);
    for (int t = 0; t < 8; t++) {
        k_path<<<(NPATHS + 127) / 128, 128>>>(links, Up, bp);
        k_link<<<(NLINKS + 127) / 128, 128>>>(Wl, Ul, bl, Wp, bp);
    }
    k_readout<<<NPATHS / 32, 128>>>(D1, b1, D2, b2, Wf, bf, out);
}

// round 5
// speedup vs baseline: 1.0043x; 1.0043x over previous
#include <cuda_runtime.h>

#define NPATHS 100000
#define NLINKS 10000

// ---------------- persistent device state ----------------
__device__ __align__(16) float g_link_state[NLINKS * 32];
__device__ __align__(16) float g_path_state[NPATHS * 32];
__device__ __align__(16) float g_m[NLINKS * 32];          // segment sums
__device__ __align__(16) float g_LG[NLINKS * 96];         // link_state @ Wp + biases

// ---------------- packed f32x2 helpers (Blackwell) ----------------
typedef unsigned long long u64;

__device__ __forceinline__ u64 splat2(float x) {
    u64 r; asm("mov.b64 %0, {%1, %1};" : "=l"(r) : "f"(x)); return r;
}
__device__ __forceinline__ u64 pack2(float a, float b) {
    u64 r; asm("mov.b64 %0, {%1, %2};" : "=l"(r) : "f"(a), "f"(b)); return r;
}
__device__ __forceinline__ void unpack2(u64 v, float& a, float& b) {
    asm("mov.b64 {%0, %1}, %2;" : "=f"(a), "=f"(b) : "l"(v));
}
__device__ __forceinline__ void ffma2(u64& d, u64 a, u64 b) {
    asm("fma.rn.f32x2 %0, %1, %2, %0;" : "+l"(d) : "l"(a), "l"(b));
}
__device__ __forceinline__ void lds_v2(unsigned addr, u64& a, u64& b) {
    asm volatile("ld.shared.v2.u64 {%0, %1}, [%2];" : "=l"(a), "=l"(b) : "r"(addr));
}
__device__ __forceinline__ void ldg_v2(const void* p, u64& a, u64& b) {
    asm volatile("ld.global.nc.v2.u64 {%0, %1}, [%2];" : "=l"(a), "=l"(b) : "l"(p));
}

// ---------------- fast activations ----------------
__device__ __forceinline__ float sigmoidf_(float x) {
    return __fdividef(1.0f, 1.0f + __expf(-x));
}
__device__ __forceinline__ float tanhfast_(float x) {
    float e = __expf(2.0f * x);
    return 1.0f - __fdividef(2.0f, e + 1.0f);
}
__device__ __forceinline__ float seluf_(float x) {
    const float sc = 1.0507009873554805f;
    const float al = 1.6732632423543772f;
    return x > 0.0f ? sc * x : sc * al * (__expf(x) - 1.0f);
}

__device__ __forceinline__ void red_add_f4(float* p, float a, float b, float c, float d) {
#if defined(__CUDA_ARCH__) && (__CUDA_ARCH__ >= 900)
    atomicAdd(reinterpret_cast<float4*>(p), make_float4(a, b, c, d));
#else
    atomicAdd(p + 0, a); atomicAdd(p + 1, b); atomicAdd(p + 2, c); atomicAdd(p + 3, d);
#endif
}

// ---------------- init: states, m=0, initial LG ----------------
__global__ void k_init(const float* __restrict__ cap, const float* __restrict__ traffic,
                       const float* __restrict__ Wp, const float* __restrict__ bp) {
    int idx = blockIdx.x * blockDim.x + threadIdx.x;
    if (idx < NPATHS * 32)
        g_path_state[idx] = ((idx & 31) == 0) ? traffic[idx >> 5] : 0.0f;
    if (idx < NLINKS * 32) {
        g_link_state[idx] = ((idx & 31) == 0) ? cap[idx >> 5] : 0.0f;
        g_m[idx] = 0.0f;
    }
    if (idx < NLINKS * 96) {
        int l = idx / 96;
        int j = idx - l * 96;
        float v = cap[l] * Wp[j] + bp[j];        // input bias bp[0]
        if (j < 64) v += bp[96 + j];             // fold recurrent bias bp[1] for z,r
        g_LG[idx] = v;
    }
}

// ---------------- path phase: 8 GRU steps + fused atomic segment-sum --------
__global__ void __launch_bounds__(128)
k_path(const int* __restrict__ links, const float* __restrict__ Up,
       const float* __restrict__ bp) {
    __shared__ __align__(16) float sUp[32 * 96];   // recurrent weights, row-major
    __shared__ u64 sb1h2[16];                      // bp[1] h-gate, packed pairs
    __shared__ float sh[32 * 132];                 // h, [k][tid] with padded stride

    const int tid = threadIdx.x;
    for (int i = tid; i < 3072; i += 128) sUp[i] = Up[i];
    if (tid < 16) sb1h2[tid] = pack2(bp[96 + 64 + 2 * tid], bp[96 + 64 + 2 * tid + 1]);

    const int p0 = blockIdx.x * 128;
    for (int i = tid; i < 4096; i += 128) {
        int r = i >> 5, c = i & 31;
        int pp = p0 + r;
        sh[c * 132 + r] = (pp < NPATHS) ? g_path_state[pp * 32 + c] : 0.0f;
    }
    __syncthreads();

    const unsigned sUp_a = (unsigned)__cvta_generic_to_shared(sUp);
    const int p = p0 + tid;
    const bool valid = (p < NPATHS);

    int lk[8];
    if (valid) {
        const int4* lp = reinterpret_cast<const int4*>(links + p * 8);
        int4 a = __ldg(lp), b = __ldg(lp + 1);
        lk[0] = a.x; lk[1] = a.y; lk[2] = a.z; lk[3] = a.w;
        lk[4] = b.x; lk[5] = b.y; lk[6] = b.z; lk[7] = b.w;
    }

    if (valid) {
        #pragma unroll 1
        for (int s = 0; s < 8; s++) {
            const char* lgb = reinterpret_cast<const char*>(g_LG + lk[s] * 96);

            u64 az2[16], ar2[16], ah2[16];
            #pragma unroll
            for (int c = 0; c < 8; c++) ldg_v2(lgb + c * 16, az2[2*c], az2[2*c+1]);
            #pragma unroll
            for (int c = 0; c < 8; c++) ldg_v2(lgb + 128 + c * 16, ar2[2*c], ar2[2*c+1]);
            #pragma unroll
            for (int i = 0; i < 16; i++) ah2[i] = sb1h2[i];

            // fused 3-gate recurrent matvec, packed f32x2
            #pragma unroll 1
            for (int k = 0; k < 32; k++) {
                float hk = sh[k * 132 + tid];
                u64 h2 = splat2(hk);
                unsigned wa = sUp_a + k * 384;
                #pragma unroll
                for (int c = 0; c < 8; c++) {
                    u64 w0, w1; lds_v2(wa + c * 16, w0, w1);
                    ffma2(az2[2*c], h2, w0); ffma2(az2[2*c+1], h2, w1);
                }
                #pragma unroll
                for (int c = 0; c < 8; c++) {
                    u64 w0, w1; lds_v2(wa + 128 + c * 16, w0, w1);
                    ffma2(ar2[2*c], h2, w0); ffma2(ar2[2*c+1], h2, w1);
                }
                #pragma unroll
                for (int c = 0; c < 8; c++) {
                    u64 w0, w1; lds_v2(wa + 256 + c * 16, w0, w1);
                    ffma2(ah2[2*c], h2, w0); ffma2(ah2[2*c+1], h2, w1);
                }
            }

            // gates + state update + fused segment-sum
            float* mrow = g_m + lk[s] * 32;
            #pragma unroll
            for (int c = 0; c < 8; c++) {
                float4 g = __ldg(reinterpret_cast<const float4*>(lgb + 256) + c);
                float a[4], r[4], hh[4], nh[4];
                unpack2(az2[2*c], a[0], a[1]);  unpack2(az2[2*c+1], a[2], a[3]);
                unpack2(ar2[2*c], r[0], r[1]);  unpack2(ar2[2*c+1], r[2], r[3]);
                unpack2(ah2[2*c], hh[0], hh[1]); unpack2(ah2[2*c+1], hh[2], hh[3]);
                #pragma unroll
                for (int u = 0; u < 4; u++) {
                    int j = 4 * c + u;
                    float z  = sigmoidf_(a[u]);
                    float rr = sigmoidf_(r[u]);
                    float cc = tanhfast_((&g.x)[u] + rr * hh[u]);
                    float ho = sh[j * 132 + tid];
                    float hn = cc + z * (ho - cc);
                    sh[j * 132 + tid] = hn;
                    nh[u] = hn;
                }
                red_add_f4(mrow + 4 * c, nh[0], nh[1], nh[2], nh[3]);
            }
        }
    }

    __syncthreads();
    for (int i = tid; i < 4096; i += 128) {
        int r = i >> 5, c = i & 31;
        int pp = p0 + r;
        if (pp < NPATHS) g_path_state[pp * 32 + c] = sh[c * 132 + r];
    }
}

// ---------------- link phase: link GRU + recompute LG + zero m --------------
__global__ void __launch_bounds__(128)
k_link(const float* __restrict__ Wl, const float* __restrict__ Ul,
       const float* __restrict__ bl, const float* __restrict__ Wp,
       const float* __restrict__ bp) {
    __shared__ float sWl[3072], sUl[3072], sWp[3072];
    __shared__ float sbl[192], sbp[192];
    const int tid = threadIdx.x;
    for (int i = tid; i < 3072; i += 128) { sWl[i] = Wl[i]; sUl[i] = Ul[i]; sWp[i] = Wp[i]; }
    for (int i = tid; i < 192; i += 128)  { sbl[i] = bl[i]; sbp[i] = bp[i]; }
    __syncthreads();

    const int l = blockIdx.x * 128 + tid;
    if (l >= NLINKS) return;

    const float* mrow = g_m + l * 32;
    float* hrow = g_link_state + l * 32;

    float az[32], ar[32], axh[32], ahh[32];
    #pragma unroll
    for (int j = 0; j < 32; j++) {
        az[j]  = sbl[j]       + sbl[96 + j];
        ar[j]  = sbl[32 + j]  + sbl[128 + j];
        axh[j] = sbl[64 + j];
        ahh[j] = sbl[160 + j];
    }

    #pragma unroll 1
    for (int k = 0; k < 32; k++) {
        float mk = __ldg(mrow + k);
        float hk = __ldg(hrow + k);
        const float4* wl = reinterpret_cast<const float4*>(sWl + k * 96);
        const float4* ul = reinterpret_cast<const float4*>(sUl + k * 96);
        #pragma unroll
        for (int c = 0; c < 8; c++) {
            float4 w = wl[c], u = ul[c];
            az[4*c+0] = fmaf(mk, w.x, fmaf(hk, u.x, az[4*c+0]));
            az[4*c+1] = fmaf(mk, w.y, fmaf(hk, u.y, az[4*c+1]));
            az[4*c+2] = fmaf(mk, w.z, fmaf(hk, u.z, az[4*c+2]));
            az[4*c+3] = fmaf(mk, w.w, fmaf(hk, u.w, az[4*c+3]));
        }
        #pragma unroll
        for (int c = 0; c < 8; c++) {
            float4 w = wl[8 + c], u = ul[8 + c];
            ar[4*c+0] = fmaf(mk, w.x, fmaf(hk, u.x, ar[4*c+0]));
            ar[4*c+1] = fmaf(mk, w.y, fmaf(hk, u.y, ar[4*c+1]));
            ar[4*c+2] = fmaf(mk, w.z, fmaf(hk, u.z, ar[4*c+2]));
            ar[4*c+3] = fmaf(mk, w.w, fmaf(hk, u.w, ar[4*c+3]));
        }
        #pragma unroll
        for (int c = 0; c < 8; c++) {
            float4 w = wl[16 + c], u = ul[16 + c];
            axh[4*c+0] = fmaf(mk, w.x, axh[4*c+0]);
            axh[4*c+1] = fmaf(mk, w.y, axh[4*c+1]);
            axh[4*c+2] = fmaf(mk, w.z, axh[4*c+2]);
            axh[4*c+3] = fmaf(mk, w.w, axh[4*c+3]);
            ahh[4*c+0] = fmaf(hk, u.x, ahh[4*c+0]);
            ahh[4*c+1] = fmaf(hk, u.y, ahh[4*c+1]);
            ahh[4*c+2] = fmaf(hk, u.z, ahh[4*c+2]);
            ahh[4*c+3] = fmaf(hk, u.w, ahh[4*c+3]);
        }
    }

    float hn[32];
    #pragma unroll
    for (int j = 0; j < 32; j++) {
        float z  = sigmoidf_(az[j]);
        float r  = sigmoidf_(ar[j]);
        float cc = tanhfast_(axh[j] + r * ahh[j]);
        float ho = __ldg(hrow + j);
        hn[j] = cc + z * (ho - cc);
    }

    float4* h4 = reinterpret_cast<float4*>(hrow);
    float4* m4 = reinterpret_cast<float4*>(g_m + l * 32);
    #pragma unroll
    for (int c = 0; c < 8; c++) {
        h4[c] = make_float4(hn[4*c], hn[4*c+1], hn[4*c+2], hn[4*c+3]);
        m4[c] = make_float4(0.f, 0.f, 0.f, 0.f);
    }

    // recompute LG = new_link_state @ Wp + biases
    float4* lg4 = reinterpret_cast<float4*>(g_LG + l * 96);
    #pragma unroll 1
    for (int jc = 0; jc < 24; jc++) {
        int j = 4 * jc;
        float a0 = sbp[j + 0], a1 = sbp[j + 1], a2 = sbp[j + 2], a3 = sbp[j + 3];
        if (jc < 16) { a0 += sbp[96+j+0]; a1 += sbp[96+j+1]; a2 += sbp[96+j+2]; a3 += sbp[96+j+3]; }
        #pragma unroll
        for (int k = 0; k < 32; k++) {
            float4 w = reinterpret_cast<const float4*>(sWp + k * 96)[jc];
            a0 = fmaf(hn[k], w.x, a0);
            a1 = fmaf(hn[k], w.y, a1);
            a2 = fmaf(hn[k], w.z, a2);
            a3 = fmaf(hn[k], w.w, a3);
        }
        lg4[jc] = make_float4(a0, a1, a2, a3);
    }
}

// ---------------- readout: lane-contiguous columns + f32x2 ------------------
__global__ void __launch_bounds__(128)
k_readout(const float* __restrict__ D1, const float* __restrict__ b1,
          const float* __restrict__ D2, const float* __restrict__ b2,
          const float* __restrict__ Wf, const float* __restrict__ bf,
          float* __restrict__ out) {
    __shared__ float sx1[4 * 8 * 256];   // per-warp [path][k] hidden1
    const int tid = threadIdx.x;
    const int lane = tid & 31, warp = tid >> 5;
    const int pbase = blockIdx.x * 32 + warp * 8;   // 100000 % 32 == 0
    float* myx1 = sx1 + warp * 2048;
    const int cb = 8 * lane;             // this lane's contiguous column base

    // hoisted biases for this lane's 8 columns
    u64 bb1[4], bb2[4];
    ldg_v2(b1 + cb, bb1[0], bb1[1]);  ldg_v2(b1 + cb + 4, bb1[2], bb1[3]);
    ldg_v2(b2 + cb, bb2[0], bb2[1]);  ldg_v2(b2 + cb + 4, bb2[2], bb2[3]);

    float hsave[8];

    // ---- layer 1: 32 -> 256 + selu ----
    #pragma unroll 1
    for (int p = 0; p < 8; p++) {
        float hown = g_path_state[(pbase + p) * 32 + lane];
        hsave[p] = hown;
        u64 acc[4];
        #pragma unroll
        for (int i = 0; i < 4; i++) acc[i] = bb1[i];
        #pragma unroll 1
        for (int k = 0; k < 32; k++) {
            float hk = __shfl_sync(0xffffffffu, hown, k);
            u64 h2 = splat2(hk);
            const float* d1 = D1 + k * 256 + cb;
            u64 w0, w1, w2, w3;
            ldg_v2(d1, w0, w1); ldg_v2(d1 + 4, w2, w3);
            ffma2(acc[0], h2, w0); ffma2(acc[1], h2, w1);
            ffma2(acc[2], h2, w2); ffma2(acc[3], h2, w3);
        }
        float2* dst = reinterpret_cast<float2*>(myx1 + p * 256 + cb);
        #pragma unroll
        for (int i = 0; i < 4; i++) {
            float x0, x1; unpack2(acc[i], x0, x1);
            dst[i] = make_float2(seluf_(x0), seluf_(x1));
        }
    }
    __syncwarp();

    // ---- layer 2: 256 -> 256, f32x2, register-reuse of D2 across 8 paths ----
    u64 a2p[32];
    #pragma unroll
    for (int p = 0; p < 8; p++)
        #pragma unroll
        for (int i = 0; i < 4; i++) a2p[p * 4 + i] = bb2[i];

    #pragma unroll 1
    for (int k = 0; k < 256; k++) {
        const float* d2 = D2 + k * 256 + cb;
        u64 w0, w1, w2, w3;
        ldg_v2(d2, w0, w1); ldg_v2(d2 + 4, w2, w3);
        #pragma unroll
        for (int p = 0; p < 8; p++) {
            u64 x2 = splat2(myx1[p * 256 + k]);
            ffma2(a2p[p*4+0], x2, w0); ffma2(a2p[p*4+1], x2, w1);
            ffma2(a2p[p*4+2], x2, w2); ffma2(a2p[p*4+3], x2, w3);
        }
    }

    // ---- selu + final dense on concat(x2, h) ----
    const float2* Wf2 = reinterpret_cast<const float2*>(Wf);
    float2 wfx[8];
    #pragma unroll
    for (int i = 0; i < 8; i++) wfx[i] = __ldg(Wf2 + cb + i);
    float2 wfh = __ldg(Wf2 + 256 + lane);
    float bf0 = __ldg(bf), bf1 = __ldg(bf + 1);

    #pragma unroll 1
    for (int p = 0; p < 8; p++) {
        float hv = hsave[p];
        float s0 = hv * wfh.x, s1 = hv * wfh.y;
        #pragma unroll
        for (int i = 0; i < 4; i++) {
            float x0, x1; unpack2(a2p[p * 4 + i], x0, x1);
            x0 = seluf_(x0); x1 = seluf_(x1);
            s0 = fmaf(x0, wfx[2*i].x, fmaf(x1, wfx[2*i+1].x, s0));
            s1 = fmaf(x0, wfx[2*i].y, fmaf(x1, wfx[2*i+1].y, s1));
        }
        #pragma unroll
        for (int off = 16; off; off >>= 1) {
            s0 += __shfl_xor_sync(0xffffffffu, s0, off);
            s1 += __shfl_xor_sync(0xffffffffu, s1, off);
        }
        if (lane == 0)
            reinterpret_cast<float2*>(out)[pbase + p] = make_float2(s0 + bf0, s1 + bf1);
    }
}

// ---------------- launch ----------------
extern "C" void kernel_launch(void* const* d_in, const int* in_sizes, int n_in,
                              void* d_out, int out_size) {
    const float* cap     = (const float*)d_in[0];
    const float* traffic = (const float*)d_in[1];
    const int*   links   = (const int*)  d_in[2];
    const float* Wp = (const float*)d_in[5];
    const float* Up = (const float*)d_in[6];
    const float* bp = (const float*)d_in[7];
    const float* Wl = (const float*)d_in[8];
    const float* Ul = (const float*)d_in[9];
    const float* bl = (const float*)d_in[10];
    const float* D1 = (const float*)d_in[11];
    const float* b1 = (const float*)d_in[12];
    const float* D2 = (const float*)d_in[13];
    const float* b2 = (const float*)d_in[14];
    const float* Wf = (const float*)d_in[15];
    const float* bf = (const float*)d_in[16];
    float* out = (float*)d_out;

    k_init<<<(NPATHS * 32 + 255) / 256, 256>>>(cap, traffic, Wp, bp);
    for (int t = 0; t < 8; t++) {
        k_path<<<(NPATHS + 127) / 128, 128>>>(links, Up, bp);
        k_link<<<(NLINKS + 127) / 128, 128>>>(Wl, Ul, bl, Wp, bp);
    }
    k_readout<<<NPATHS / 32, 128>>>(D1, b1, D2, b2, Wf, bf, out);
}

// round 6
// speedup vs baseline: 1.4724x; 1.4662x over previous
#include <cuda_runtime.h>

#define NPATHS 100000
#define NLINKS 10000

// ---------------- persistent device state ----------------
__device__ __align__(16) float g_link_state[NLINKS * 32];
__device__ __align__(16) float g_path_state[NPATHS * 32];
__device__ __align__(16) float g_m[NLINKS * 32];          // segment sums
__device__ __align__(16) float g_LG[NLINKS * 96];         // link_state @ Wp + biases

// ---------------- packed f32x2 helpers ----------------
typedef unsigned long long u64;

__device__ __forceinline__ u64 splat2(float x) {
    u64 r; asm("mov.b64 %0, {%1, %1};" : "=l"(r) : "f"(x)); return r;
}
__device__ __forceinline__ u64 pack2(float a, float b) {
    u64 r; asm("mov.b64 %0, {%1, %2};" : "=l"(r) : "f"(a), "f"(b)); return r;
}
__device__ __forceinline__ void unpack2(u64 v, float& a, float& b) {
    asm("mov.b64 {%0, %1}, %2;" : "=f"(a), "=f"(b) : "l"(v));
}
__device__ __forceinline__ void ffma2(u64& d, u64 a, u64 b) {
    asm("fma.rn.f32x2 %0, %1, %2, %0;" : "+l"(d) : "l"(a), "l"(b));
}
__device__ __forceinline__ u64 lds_b64(unsigned addr) {
    u64 r; asm volatile("ld.shared.b64 %0, [%1];" : "=l"(r) : "r"(addr)); return r;
}
__device__ __forceinline__ void ldg_v2(const void* p, u64& a, u64& b) {
    asm volatile("ld.global.nc.v2.u64 {%0, %1}, [%2];" : "=l"(a), "=l"(b) : "l"(p));
}

// ---------------- fast activations ----------------
__device__ __forceinline__ float sigmoidf_(float x) {
    return __fdividef(1.0f, 1.0f + __expf(-x));
}
__device__ __forceinline__ float tanhfast_(float x) {
    float e = __expf(2.0f * x);
    return 1.0f - __fdividef(2.0f, e + 1.0f);
}
__device__ __forceinline__ float seluf_(float x) {
    const float sc = 1.0507009873554805f;
    const float al = 1.6732632423543772f;
    return x > 0.0f ? sc * x : sc * al * (__expf(x) - 1.0f);
}

// ---------------- init: states, m=0, initial LG ----------------
__global__ void k_init(const float* __restrict__ cap, const float* __restrict__ traffic,
                       const float* __restrict__ Wp, const float* __restrict__ bp) {
    int idx = blockIdx.x * blockDim.x + threadIdx.x;
    if (idx < NPATHS * 32)
        g_path_state[idx] = ((idx & 31) == 0) ? traffic[idx >> 5] : 0.0f;
    if (idx < NLINKS * 32) {
        g_link_state[idx] = ((idx & 31) == 0) ? cap[idx >> 5] : 0.0f;
        g_m[idx] = 0.0f;
    }
    if (idx < NLINKS * 96) {
        int l = idx / 96;
        int j = idx - l * 96;
        float v = cap[l] * Wp[j] + bp[j];        // input bias bp[0]
        if (j < 64) v += bp[96 + j];             // fold recurrent bias bp[1] for z,r
        g_LG[idx] = v;
    }
}

// ---------------- path phase v3: lane=dim, warp=16 paths --------------------
// Gather & segment-sum fully coalesced; f32x2 accumulators pair-packed over paths.
#define PPW 16          // paths per warp
#define NPAIR 8         // path pairs per warp
#define HSTR 9          // u64 stride per dim row (8 pairs + 1 pad)

__global__ void __launch_bounds__(128)
k_path(const int* __restrict__ links, const float* __restrict__ Up,
       const float* __restrict__ bp) {
    __shared__ __align__(16) float sUp[3072];          // Up [k][j] row-major
    __shared__ int slinks[64 * 8];                     // 64 paths per block
    __shared__ __align__(16) u64 sh2[4 * 32 * HSTR];   // per warp: h[dim][pair]

    const int tid  = threadIdx.x;
    const int lane = tid & 31;
    const int warp = tid >> 5;
    const int p0   = blockIdx.x * 64;                  // 64 paths per block

    for (int i = tid; i < 3072; i += 128) sUp[i] = Up[i];
    for (int i = tid; i < 512; i += 128) {
        int e = p0 * 8 + i;
        slinks[i] = (e < NPATHS * 8) ? links[e] : 0;
    }
    __syncthreads();

    const int pw = p0 + warp * PPW;
    if (pw >= NPATHS) return;                          // whole-warp exit, no later bars

    u64* shw = sh2 + warp * 32 * HSTR;
    float* shf = reinterpret_cast<float*>(shw);

    // load h tile: path i dims coalesced; float idx = dim*2*HSTR + i
    #pragma unroll 1
    for (int i = 0; i < PPW; i++)
        shf[lane * 2 * HSTR + i] = g_path_state[(pw + i) * 32 + lane];

    const u64 b1h2 = splat2(__ldg(bp + 96 + 64 + lane));
    const unsigned shw_a = (unsigned)__cvta_generic_to_shared(shw);
    const int* slk = slinks + warp * PPW * 8;

    #pragma unroll 1
    for (int s = 0; s < 8; s++) {
        u64 accz[NPAIR], accr[NPAIR], acch[NPAIR];

        // init accumulators with LG z/r parts (coalesced LDG.32 per path)
        #pragma unroll
        for (int p2 = 0; p2 < NPAIR; p2++) {
            int lkA = slk[(2 * p2) * 8 + s];
            int lkB = slk[(2 * p2 + 1) * 8 + s];
            const float* lgA = g_LG + lkA * 96 + lane;
            const float* lgB = g_LG + lkB * 96 + lane;
            accz[p2] = pack2(__ldg(lgA), __ldg(lgB));
            accr[p2] = pack2(__ldg(lgA + 32), __ldg(lgB + 32));
            acch[p2] = b1h2;
        }

        // recurrent matvec: per k, 3 coalesced weight LDS + 8 broadcast pair loads
        #pragma unroll 1
        for (int k = 0; k < 32; k++) {
            const float* w = sUp + k * 96 + lane;
            u64 wz2 = splat2(w[0]);
            u64 wr2 = splat2(w[32]);
            u64 wh2 = splat2(w[64]);
            unsigned ha = shw_a + (unsigned)(k * HSTR * 8);
            #pragma unroll
            for (int p2 = 0; p2 < NPAIR; p2++) {
                u64 h2 = lds_b64(ha + p2 * 8);
                ffma2(accz[p2], h2, wz2);
                ffma2(accr[p2], h2, wr2);
                ffma2(acch[p2], h2, wh2);
            }
        }

        // gates + state update + coalesced segment-sum
        #pragma unroll
        for (int p2 = 0; p2 < NPAIR; p2++) {
            int lkA = slk[(2 * p2) * 8 + s];
            int lkB = slk[(2 * p2 + 1) * 8 + s];
            float ghA = __ldg(g_LG + lkA * 96 + 64 + lane);
            float ghB = __ldg(g_LG + lkB * 96 + 64 + lane);
            float azA, azB, arA, arB, ahA, ahB;
            unpack2(accz[p2], azA, azB);
            unpack2(accr[p2], arA, arB);
            unpack2(acch[p2], ahA, ahB);
            float* hp = shf + lane * 2 * HSTR + 2 * p2;

            float zA = sigmoidf_(azA);
            float rA = sigmoidf_(arA);
            float cA = tanhfast_(ghA + rA * ahA);
            float hoA = hp[0];
            float hnA = cA + zA * (hoA - cA);
            hp[0] = hnA;
            atomicAdd(g_m + lkA * 32 + lane, hnA);

            float zB = sigmoidf_(azB);
            float rB = sigmoidf_(arB);
            float cB = tanhfast_(ghB + rB * ahB);
            float hoB = hp[1];
            float hnB = cB + zB * (hoB - cB);
            hp[1] = hnB;
            atomicAdd(g_m + lkB * 32 + lane, hnB);
        }
    }

    // writeback h tile (coalesced per path)
    #pragma unroll 1
    for (int i = 0; i < PPW; i++)
        g_path_state[(pw + i) * 32 + lane] = shf[lane * 2 * HSTR + i];
}

// ---------------- link phase v2: warp per link, lane=dim --------------------
__global__ void __launch_bounds__(256)
k_link(const float* __restrict__ Wl, const float* __restrict__ Ul,
       const float* __restrict__ bl, const float* __restrict__ Wp,
       const float* __restrict__ bp) {
    __shared__ float sWl[3072], sUl[3072], sWp[3072];
    __shared__ float sbl[192], sbp[192];
    const int tid = threadIdx.x;
    for (int i = tid; i < 3072; i += 256) { sWl[i] = Wl[i]; sUl[i] = Ul[i]; sWp[i] = Wp[i]; }
    if (tid < 192) { sbl[tid] = bl[tid]; sbp[tid] = bp[tid]; }
    __syncthreads();

    const int lane = tid & 31;
    const int L = blockIdx.x * 8 + (tid >> 5);        // 1250 * 8 = 10000 exact

    float mown = g_m[L * 32 + lane];
    float hown = g_link_state[L * 32 + lane];

    float az  = sbl[lane]      + sbl[96 + lane];
    float arx = sbl[32 + lane] + sbl[128 + lane];
    float axh = sbl[64 + lane];
    float ahh = sbl[160 + lane];

    #pragma unroll 1
    for (int k = 0; k < 32; k++) {
        float mk = __shfl_sync(0xffffffffu, mown, k);
        float hk = __shfl_sync(0xffffffffu, hown, k);
        const float* wl = sWl + k * 96 + lane;
        const float* ul = sUl + k * 96 + lane;
        az  = fmaf(mk, wl[0],  fmaf(hk, ul[0],  az));
        arx = fmaf(mk, wl[32], fmaf(hk, ul[32], arx));
        axh = fmaf(mk, wl[64], axh);
        ahh = fmaf(hk, ul[64], ahh);
    }

    float z  = sigmoidf_(az);
    float r  = sigmoidf_(arx);
    float c  = tanhfast_(axh + r * ahh);
    float hn = c + z * (hown - c);

    g_link_state[L * 32 + lane] = hn;
    g_m[L * 32 + lane] = 0.0f;                        // reset for next iteration

    // recompute LG = new_link_state @ Wp + biases (lane owns cols j, 32+j, 64+j)
    float l0 = sbp[lane]      + sbp[96 + lane];
    float l1 = sbp[32 + lane] + sbp[128 + lane];
    float l2 = sbp[64 + lane];
    #pragma unroll 1
    for (int k = 0; k < 32; k++) {
        float hk = __shfl_sync(0xffffffffu, hn, k);
        const float* wp = sWp + k * 96 + lane;
        l0 = fmaf(hk, wp[0],  l0);
        l1 = fmaf(hk, wp[32], l1);
        l2 = fmaf(hk, wp[64], l2);
    }
    g_LG[L * 96 + lane]      = l0;
    g_LG[L * 96 + 32 + lane] = l1;
    g_LG[L * 96 + 64 + lane] = l2;
}

// ---------------- readout: lane-contiguous columns + f32x2 ------------------
__global__ void __launch_bounds__(128)
k_readout(const float* __restrict__ D1, const float* __restrict__ b1,
          const float* __restrict__ D2, const float* __restrict__ b2,
          const float* __restrict__ Wf, const float* __restrict__ bf,
          float* __restrict__ out) {
    __shared__ float sx1[4 * 8 * 256];   // per-warp [path][k] hidden1
    const int tid = threadIdx.x;
    const int lane = tid & 31, warp = tid >> 5;
    const int pbase = blockIdx.x * 32 + warp * 8;   // 100000 % 32 == 0
    float* myx1 = sx1 + warp * 2048;
    const int cb = 8 * lane;             // this lane's contiguous column base

    u64 bb1[4], bb2[4];
    ldg_v2(b1 + cb, bb1[0], bb1[1]);  ldg_v2(b1 + cb + 4, bb1[2], bb1[3]);
    ldg_v2(b2 + cb, bb2[0], bb2[1]);  ldg_v2(b2 + cb + 4, bb2[2], bb2[3]);

    float hsave[8];

    // ---- layer 1: 32 -> 256 + selu ----
    #pragma unroll 1
    for (int p = 0; p < 8; p++) {
        float hown = g_path_state[(pbase + p) * 32 + lane];
        hsave[p] = hown;
        u64 acc[4];
        #pragma unroll
        for (int i = 0; i < 4; i++) acc[i] = bb1[i];
        #pragma unroll 1
        for (int k = 0; k < 32; k++) {
            float hk = __shfl_sync(0xffffffffu, hown, k);
            u64 h2 = splat2(hk);
            const float* d1 = D1 + k * 256 + cb;
            u64 w0, w1, w2, w3;
            ldg_v2(d1, w0, w1); ldg_v2(d1 + 4, w2, w3);
            ffma2(acc[0], h2, w0); ffma2(acc[1], h2, w1);
            ffma2(acc[2], h2, w2); ffma2(acc[3], h2, w3);
        }
        float2* dst = reinterpret_cast<float2*>(myx1 + p * 256 + cb);
        #pragma unroll
        for (int i = 0; i < 4; i++) {
            float x0, x1; unpack2(acc[i], x0, x1);
            dst[i] = make_float2(seluf_(x0), seluf_(x1));
        }
    }
    __syncwarp();

    // ---- layer 2: 256 -> 256, f32x2, D2-row reuse across 8 paths ----
    u64 a2p[32];
    #pragma unroll
    for (int p = 0; p < 8; p++)
        #pragma unroll
        for (int i = 0; i < 4; i++) a2p[p * 4 + i] = bb2[i];

    #pragma unroll 1
    for (int k = 0; k < 256; k++) {
        const float* d2 = D2 + k * 256 + cb;
        u64 w0, w1, w2, w3;
        ldg_v2(d2, w0, w1); ldg_v2(d2 + 4, w2, w3);
        #pragma unroll
        for (int p = 0; p < 8; p++) {
            u64 x2 = splat2(myx1[p * 256 + k]);
            ffma2(a2p[p*4+0], x2, w0); ffma2(a2p[p*4+1], x2, w1);
            ffma2(a2p[p*4+2], x2, w2); ffma2(a2p[p*4+3], x2, w3);
        }
    }

    // ---- selu + final dense on concat(x2, h) ----
    const float2* Wf2 = reinterpret_cast<const float2*>(Wf);
    float2 wfx[8];
    #pragma unroll
    for (int i = 0; i < 8; i++) wfx[i] = __ldg(Wf2 + cb + i);
    float2 wfh = __ldg(Wf2 + 256 + lane);
    float bf0 = __ldg(bf), bf1 = __ldg(bf + 1);

    #pragma unroll 1
    for (int p = 0; p < 8; p++) {
        float hv = hsave[p];
        float s0 = hv * wfh.x, s1 = hv * wfh.y;
        #pragma unroll
        for (int i = 0; i < 4; i++) {
            float x0, x1; unpack2(a2p[p * 4 + i], x0, x1);
            x0 = seluf_(x0); x1 = seluf_(x1);
            s0 = fmaf(x0, wfx[2*i].x, fmaf(x1, wfx[2*i+1].x, s0));
            s1 = fmaf(x0, wfx[2*i].y, fmaf(x1, wfx[2*i+1].y, s1));
        }
        #pragma unroll
        for (int off = 16; off; off >>= 1) {
            s0 += __shfl_xor_sync(0xffffffffu, s0, off);
            s1 += __shfl_xor_sync(0xffffffffu, s1, off);
        }
        if (lane == 0)
            reinterpret_cast<float2*>(out)[pbase + p] = make_float2(s0 + bf0, s1 + bf1);
    }
}

// ---------------- launch ----------------
extern "C" void kernel_launch(void* const* d_in, const int* in_sizes, int n_in,
                              void* d_out, int out_size) {
    const float* cap     = (const float*)d_in[0];
    const float* traffic = (const float*)d_in[1];
    const int*   links   = (const int*)  d_in[2];
    const float* Wp = (const float*)d_in[5];
    const float* Up = (const float*)d_in[6];
    const float* bp = (const float*)d_in[7];
    const float* Wl = (const float*)d_in[8];
    const float* Ul = (const float*)d_in[9];
    const float* bl = (const float*)d_in[10];
    const float* D1 = (const float*)d_in[11];
    const float* b1 = (const float*)d_in[12];
    const float* D2 = (const float*)d_in[13];
    const float* b2 = (const float*)d_in[14];
    const float* Wf = (const float*)d_in[15];
    const float* bf = (const float*)d_in[16];
    float* out = (float*)d_out;

    k_init<<<(NPATHS * 32 + 255) / 256, 256>>>(cap, traffic, Wp, bp);
    for (int t = 0; t < 8; t++) {
        k_path<<<(NPATHS + 63) / 64, 128>>>(links, Up, bp);
        k_link<<<NLINKS / 8, 256>>>(Wl, Ul, bl, Wp, bp);
    }
    k_readout<<<NPATHS / 32, 128>>>(D1, b1, D2, b2, Wf, bf, out);
}